// round 4
// baseline (speedup 1.0000x reference)
#include <cuda_runtime.h>
#include <cstdint>

#define DIMZ 96
#define OUT_ROW 4753          // 1 + 96 + 96*97/2
#define G 4                   // rows per CTA
#define TPB 256
#define NVEC 4753             // float4s per CTA = G*OUT_ROW/4
#define ZSTRIDE 389           // z-copy stride: 389 % 32 == 5 (odd) -> conflict-free
#define FLAG 0x80000000u

// Per-float4 descriptor: FLAG if non-uniform, else (r<<20)|(i<<10)|j meaning
// out4[v] = z_r[i] * z_r[j..j+3]  (i==96 is the 1.0 sentinel -> linear terms).
__device__ uint32_t g_v[NVEC];
// Per-element packed (i<<8)|j pairs for the fallback path.
__device__ uint16_t g_pair[OUT_ROW];

__global__ void init_tbl_kernel() {
    int x = blockIdx.x * blockDim.x + threadIdx.x;

    // ---- per-element pair table ----
    if (x < OUT_ROW) {
        int i, j;
        if (x == 0)            { i = 96; j = 96; }
        else if (x <= DIMZ)    { i = 96; j = x - 1; }
        else {
            int q = x - DIMZ - 1;
            i = 0; int s = 0;
            while (s + (DIMZ - i) <= q) { s += DIMZ - i; ++i; }
            j = i + (q - s);
        }
        g_pair[x] = (uint16_t)((i << 8) | j);
    }

    // ---- per-float4 descriptor table ----
    if (x < NVEC) {
        int l = x << 2;
        int r = l / OUT_ROW;
        int k = l - r * OUT_ROW;
        uint32_t e = FLAG;
        if (k + 3 < OUT_ROW) {
            if (k >= 1 && k + 3 <= DIMZ) {
                // all four in the linear region: z[k-1..k+2] * 1.0
                e = ((uint32_t)r << 20) | (96u << 10) | (uint32_t)(k - 1);
            } else if (k > DIMZ) {
                // quad region: uniform iff first and last share the same i
                int q0 = k - DIMZ - 1, q3 = q0 + 3;
                int i0 = 0, s = 0;
                while (s + (DIMZ - i0) <= q0) { s += DIMZ - i0; ++i0; }
                int j0 = i0 + (q0 - s);
                int i3 = i0, s3 = s;
                while (s3 + (DIMZ - i3) <= q3) { s3 += DIMZ - i3; ++i3; }
                if (i3 == i0)
                    e = ((uint32_t)r << 20) | ((uint32_t)i0 << 10) | (uint32_t)j0;
            }
        }
        g_v[x] = e;
    }
}

__global__ __launch_bounds__(TPB) void poly_kernel(const float* __restrict__ z,
                                                   float* __restrict__ out) {
    // 4 copies of the 4-row z tile (97 floats/row, slot 96 = 1.0 sentinel).
    // Copy g serves lanes [8g, 8g+8): bank = 5g + 4u' (mod 32), all distinct.
    __shared__ float zsh[4 * ZSTRIDE];

    const int tid = threadIdx.x;
    const float* zr = z + (size_t)blockIdx.x * (G * DIMZ);

    for (int t = tid; t < 4 * G * 97; t += TPB) {
        int c   = t / (G * 97);
        int rem = t - c * (G * 97);
        int r   = rem / 97;
        int j   = rem - r * 97;
        zsh[c * ZSTRIDE + r * 97 + j] = (j < DIMZ) ? zr[r * DIMZ + j] : 1.0f;
    }
    __syncthreads();

    const float* zg = zsh + ((tid & 31) >> 3) * ZSTRIDE;
    float4* o4 = (float4*)(out + (size_t)blockIdx.x * (G * OUT_ROW));

    for (int v = tid; v < NVEC; v += TPB) {
        const uint32_t e = __ldg(&g_v[v]);
        float4 res;
        if (!(e & FLAG)) {
            // uniform: z_r[i] * z_r[j..j+3]
            const float* zb = zg + ((e >> 20) & 7u) * 97;
            const float  zi = zb[(e >> 10) & 127u];
            const int    j  = e & 1023u;
            res.x = zi * zb[j];
            res.y = zi * zb[j + 1];
            res.z = zi * zb[j + 2];
            res.w = zi * zb[j + 3];
        } else {
            // crossing float4 (~6%): per-element pair table
            const int l = v << 2;
            float vals[4];
            #pragma unroll
            for (int q = 0; q < 4; q++) {
                const int le = l + q;
                const int re = le / OUT_ROW;
                const int ke = le - re * OUT_ROW;
                const uint32_t p = g_pair[ke];
                const float* zb = zg + re * 97;
                vals[q] = zb[p >> 8] * zb[p & 255u];
            }
            res = make_float4(vals[0], vals[1], vals[2], vals[3]);
        }
        o4[v] = res;
    }
}

extern "C" void kernel_launch(void* const* d_in, const int* in_sizes, int n_in,
                              void* d_out, int out_size) {
    const float* z = (const float*)d_in[0];
    float* out = (float*)d_out;
    const int B = in_sizes[0] / DIMZ;       // 32768, divisible by G=4

    init_tbl_kernel<<<(NVEC + 255) / 256, 256>>>();
    poly_kernel<<<B / G, TPB>>>(z, out);
}